// round 15
// baseline (speedup 1.0000x reference)
#include <cuda_runtime.h>
#include <cuda_fp16.h>
#include <math.h>
#include <stdint.h>

#define S 8192
#define DM 768
#define DR 1024
#define MI 3072

// ------------------- scratch (device globals; no allocs allowed) -------------------
__device__ __half g_hh[S * DM];          // rmsnorm output (h, then h2), fp16
__device__ __half g_abr[S * DR];         // gelu(a_branch), fp16
__device__ __half g_bb[S * DR];          // b_branch, fp16
__device__ float  g_conv[S * DR];        // conv output fp32 (for gx math)
__device__ __half g_convh[S * DR];       // conv output fp16 (gates GEMM operand)
__device__ float  g_a[S * DR];           // recurrence decay
__device__ float  g_gx[S * DR];          // gated_x
__device__ __half g_ya[S * DR];          // a_branch * y, fp16 (out-GEMM operand)
__device__ float  g_x2[S * DM];          // x + tempmix
__device__ __half g_mi[S * MI];          // GLU output, fp16 (m2-GEMM operand)
// fp16 weights (converted once per launch; *_i = row-interleaved pairs)
__device__ __half g_wlin1i[2 * DR * DM];
__device__ __half g_wk[DR * 4 * DR];     // conv repacked [N=1024][K=4096]
__device__ __half g_wrgi[2 * DR * DR];
__device__ __half g_wout[DM * DR];
__device__ __half g_wm1i[2 * MI * DM];
__device__ __half g_wm2[DM * MI];
#define NCHUNK 64
#define SCHUNK 128
__device__ float g_Ag[NCHUNK * DR];
__device__ float g_Bg[NCHUNK * DR];
__device__ float g_carry[NCHUNK * DR];

// ------------------- math helpers -------------------
__device__ __forceinline__ float gelu_f(float x) {
    float x3 = x * x * x;
    return 0.5f * x * (1.0f + tanhf(0.7978845608028654f * (x + 0.044715f * x3)));
}
__device__ __forceinline__ float sigmoid_f(float x) { return 1.0f / (1.0f + expf(-x)); }

// ------------------- cp.async / ldmatrix helpers -------------------
__device__ __forceinline__ uint32_t smem_u32(const void* p) {
    uint32_t a;
    asm("{ .reg .u64 t; cvta.to.shared.u64 t, %1; cvt.u32.u64 %0, t; }" : "=r"(a) : "l"(p));
    return a;
}
#define CP16(dst, src) \
    asm volatile("cp.async.cg.shared.global [%0], [%1], 16;" :: "r"(dst), "l"(src))
#define CP16_ZFILL(dst, src) \
    asm volatile("cp.async.cg.shared.global [%0], [%1], 16, 0;" :: "r"(dst), "l"(src))
#define CP_COMMIT() asm volatile("cp.async.commit_group;" ::: "memory")
#define CP_WAIT(n) asm volatile("cp.async.wait_group %0;" :: "n"(n) : "memory")
#define LDSM_X4(r0, r1, r2, r3, addr)                                           \
    asm volatile("ldmatrix.sync.aligned.m8n8.x4.shared.b16 {%0,%1,%2,%3}, [%4];" \
                 : "=r"(r0), "=r"(r1), "=r"(r2), "=r"(r3) : "r"(addr))

// ------------------- fp16 mma.sync m16n8k16 (fp32 accum) -------------------
__device__ __forceinline__ void mma_f16(float* c, const uint32_t* a, const uint32_t* b) {
    asm volatile(
        "mma.sync.aligned.m16n8k16.row.col.f32.f16.f16.f32 "
        "{%0,%1,%2,%3}, {%4,%5,%6,%7}, {%8,%9}, {%0,%1,%2,%3};"
        : "+f"(c[0]), "+f"(c[1]), "+f"(c[2]), "+f"(c[3])
        : "r"(a[0]), "r"(a[1]), "r"(a[2]), "r"(a[3]), "r"(b[0]), "r"(b[1]));
}

// ------------------- fp16 GEMM: C[M,N] = A[M,K] @ W[N,K]^T (+fused epilogues) ------
// Tile 128x256x64, up-to-4-stage cp.async (runtime stage count), 256 threads
// (2x4 warps), warp tile 64x64. ldmatrix.x4 operand fetch (conflict-free, SK=72).
// EPI 0: conv      -> C fp32 + Cb fp16
// EPI 2: gates     -> pairwise (ig,rg): a=exp(-8 sp(lam) rg), gx=sqrt(1-a^2) ig conv
// EPI 3: +bias+res -> C fp32 (out / m2)
// EPI 4: lin1      -> pairwise: Cb2=gelu(a+bias) fp16, Cb=b+bias fp16
// EPI 5: m1+GLU    -> pairwise: Cb=gelu(u)*v fp16
#define MAXSTAGES 4
#define BM 128
#define BN 256
#define BK 64
#define SK 72                          // padded row stride in halves (64+8 -> 144B)
#define A_STG (BM * SK)                // halves per A stage
#define B_STG (BN * SK)                // halves per B stage

template <int EPI>
__global__ void __launch_bounds__(256)
tc_gemm(const __half* __restrict__ A, int lda, const __half* __restrict__ W,
        const float* __restrict__ bias, const float* __restrict__ res,
        float* __restrict__ C, int ldc, float* __restrict__ C2,
        __half* __restrict__ Cb, __half* __restrict__ Cb2,
        const float* __restrict__ aux, const float* __restrict__ lam,
        int K, int shifted, int nstages) {
    extern __shared__ __half sm[];
    __half* sA = sm;                           // nstages * A_STG
    __half* sB = sm + nstages * A_STG;         // nstages * B_STG
    const int tid = threadIdx.x, lane = tid & 31, wid = tid >> 5;
    const int wm = wid & 1, wn = wid >> 1, laneg = lane >> 2, lanet = lane & 3;
    const int bm = blockIdx.y * BM, bn = blockIdx.x * BN;
    const int ktiles = K >> 6;
    const uint32_t sAaddr = smem_u32(sA), sBaddr = smem_u32(sB);

    // ldmatrix lane-address bases (bytes), before stage/k/frag offsets
    const uint32_t aBase = sAaddr +
        (uint32_t)((wm * 64 + (lane & 15)) * SK + ((lane >> 4) << 3)) * 2u;
    const uint32_t bBase = sBaddr +
        (uint32_t)((wn * 64 + (lane & 7) + (((lane >> 4) & 1) << 3)) * SK +
                   (((lane >> 3) & 1) << 3)) * 2u;

    float acc[4][8][4];
#pragma unroll
    for (int i = 0; i < 4; i++)
#pragma unroll
        for (int j = 0; j < 8; j++)
#pragma unroll
            for (int t = 0; t < 4; t++) acc[i][j][t] = 0.f;

    auto load_stage = [&](int kt, int st) {
#pragma unroll
        for (int i = 0; i < 4; i++) {                 // A: 1024 16B chunks (128 rows x 64 halves)
            int c = tid + 256 * i;
            int row = c >> 3, kc = c & 7;
            int grow, gcol;
            if (shifted) { int seg = kt >> 4; grow = bm + row + seg - 3; gcol = ((kt & 15) << 6) + (kc << 3); }
            else { grow = bm + row; gcol = (kt << 6) + (kc << 3); }
            uint32_t dst = sAaddr + (uint32_t)(st * A_STG + row * SK + (kc << 3)) * 2u;
            const __half* src = A + (size_t)grow * lda + gcol;
            if (shifted && grow < 0) CP16_ZFILL(dst, A);
            else CP16(dst, src);
        }
#pragma unroll
        for (int i = 0; i < 8; i++) {                 // B: 2048 16B chunks (256 rows)
            int c = tid + 256 * i;
            int row = c >> 3, kc = c & 7;
            uint32_t dst = sBaddr + (uint32_t)(st * B_STG + row * SK + (kc << 3)) * 2u;
            const __half* src = W + (size_t)(bn + row) * K + (kt << 6) + (kc << 3);
            CP16(dst, src);
        }
    };

    auto compute_stage = [&](int st) {
        const uint32_t aoff = (uint32_t)(st * A_STG) * 2u;
        const uint32_t boff = (uint32_t)(st * B_STG) * 2u;
#pragma unroll
        for (int k16 = 0; k16 < 4; k16++) {
            const uint32_t kb = (uint32_t)(k16 * 16) * 2u;
            uint32_t af[4][4], bf[8][2];
#pragma unroll
            for (int mf = 0; mf < 4; mf++) {
                uint32_t addr = aBase + aoff + (uint32_t)(mf * 16 * SK) * 2u + kb;
                LDSM_X4(af[mf][0], af[mf][1], af[mf][2], af[mf][3], addr);
            }
#pragma unroll
            for (int np = 0; np < 4; np++) {
                uint32_t addr = bBase + boff + (uint32_t)(np * 16 * SK) * 2u + kb;
                LDSM_X4(bf[2 * np][0], bf[2 * np][1], bf[2 * np + 1][0], bf[2 * np + 1][1], addr);
            }
#pragma unroll
            for (int mf = 0; mf < 4; mf++)
#pragma unroll
                for (int nf = 0; nf < 8; nf++) mma_f16(acc[mf][nf], af[mf], bf[nf]);
        }
    };

    for (int s = 0; s < nstages - 1; s++) { load_stage(s, s); CP_COMMIT(); }
    int st = 0;
    for (int kt = 0; kt < ktiles; kt++) {
        if (nstages == 4) CP_WAIT(2); else CP_WAIT(1);
        __syncthreads();
        int nk = kt + nstages - 1;
        if (nk < ktiles) load_stage(nk, (st + nstages - 1) % nstages);
        CP_COMMIT();
        compute_stage(st);
        if (++st == nstages) st = 0;
    }
    CP_WAIT(0);

    // ---------------- epilogues ----------------
    if (EPI == 0 || EPI == 3) {
#pragma unroll
        for (int mf = 0; mf < 4; mf++)
#pragma unroll
            for (int half = 0; half < 2; half++) {
                int row = bm + wm * 64 + mf * 16 + laneg + half * 8;
                size_t crow = (size_t)row * ldc;
#pragma unroll
                for (int nf = 0; nf < 8; nf++) {
                    int col = bn + wn * 64 + nf * 8 + lanet * 2;
                    float v0 = acc[mf][nf][half * 2];
                    float v1 = acc[mf][nf][half * 2 + 1];
                    if (EPI == 3) {
                        v0 += bias[col] + res[crow + col];
                        v1 += bias[col + 1] + res[crow + col + 1];
                    }
                    *(float2*)&C[crow + col] = make_float2(v0, v1);
                    if (EPI == 0) {
                        __half2 hv; hv.x = __float2half(v0); hv.y = __float2half(v1);
                        *(__half2*)&Cb[crow + col] = hv;
                    }
                }
            }
    } else {  // pairwise EPIs: thread holds (2c, 2c+1)
#pragma unroll
        for (int nf = 0; nf < 8; nf++) {
            int c = (bn + wn * 64 + nf * 8 + lanet * 2) >> 1;
            float sp, b0, b1;
            if (EPI == 2) { sp = log1pf(expf(lam[c])); b0 = bias[c]; b1 = bias[DR + c]; }
            if (EPI == 4) { b0 = bias[c]; b1 = bias[DR + c]; }
            if (EPI == 5) { b0 = bias[c]; b1 = bias[MI + c]; }
#pragma unroll
            for (int mf = 0; mf < 4; mf++)
#pragma unroll
                for (int half = 0; half < 2; half++) {
                    int row = bm + wm * 64 + mf * 16 + laneg + half * 8;
                    float v0 = acc[mf][nf][half * 2] + b0;
                    float v1 = acc[mf][nf][half * 2 + 1] + b1;
                    if (EPI == 2) {
                        float ig = sigmoid_f(v0), rg = sigmoid_f(v1);
                        float a = expf(-8.0f * sp * rg);
                        float gx = sqrtf(fmaxf(1.0f - a * a, 0.f)) * ig * aux[(size_t)row * DR + c];
                        C[(size_t)row * DR + c] = a;
                        C2[(size_t)row * DR + c] = gx;
                    } else if (EPI == 4) {
                        Cb2[(size_t)row * DR + c] = __float2half(gelu_f(v0));
                        Cb[(size_t)row * DR + c] = __float2half(v1);
                    } else {  // EPI 5
                        Cb[(size_t)row * MI + c] = __float2half(gelu_f(v0) * v1);
                    }
                }
        }
    }
}

// ------------------- RMSNorm (fp16 output: feeds GEMMs) -------------------
__global__ __launch_bounds__(256) void rmsnorm_k(const float* __restrict__ x,
                                                 const float* __restrict__ w,
                                                 __half* __restrict__ o, int D) {
    int row = blockIdx.x;
    const float* xr = x + (size_t)row * D;
    float s = 0.f;
    for (int i = threadIdx.x; i < D; i += 256) { float v = xr[i]; s += v * v; }
    __shared__ float sm[8];
    __shared__ float s_inv;
    for (int off = 16; off; off >>= 1) s += __shfl_down_sync(0xffffffffu, s, off);
    if ((threadIdx.x & 31) == 0) sm[threadIdx.x >> 5] = s;
    __syncthreads();
    if (threadIdx.x == 0) {
        float t = 0.f;
#pragma unroll
        for (int i = 0; i < 8; i++) t += sm[i];
        s_inv = rsqrtf(t / (float)D + 1e-5f);
    }
    __syncthreads();
    float inv = s_inv;
    __half* orow = o + (size_t)row * D;
    for (int i = threadIdx.x; i < D; i += 256) orow[i] = __float2half(xr[i] * inv * w[i]);
}

// ------------------- weight conversion kernels -------------------
__global__ __launch_bounds__(256) void cvt_w_k(const float* __restrict__ src,
                                               __half* __restrict__ dst, int n) {
    int i = (blockIdx.x * 256 + threadIdx.x) * 4;
    if (i >= n) return;
    float4 v = *(const float4*)(src + i);
    __half2 h0; h0.x = __float2half(v.x); h0.y = __float2half(v.y);
    __half2 h1; h1.x = __float2half(v.z); h1.y = __float2half(v.w);
    *(__half2*)(dst + i) = h0;
    *(__half2*)(dst + i + 2) = h1;
}
// interleave rows: dst[2c+p][k] = src[p*Nh + c][k]
__global__ __launch_bounds__(256) void cvt_w_pair_k(const float* __restrict__ src,
                                                    __half* __restrict__ dst, int Nh, int K) {
    int i = blockIdx.x * 256 + threadIdx.x;
    if (i >= 2 * Nh * K) return;
    int n = i / K, k = i - n * K;
    int c = n >> 1, p = n & 1;
    dst[i] = __float2half(src[(size_t)(p * Nh + c) * K + k]);
}
__global__ __launch_bounds__(256) void repack_wconv_k(const float* __restrict__ w_conv) {
    int i = blockIdx.x * 256 + threadIdx.x;
    if (i >= DR * 4 * DR) return;
    int n = i >> 12;
    int rem = i & 4095;
    int t = rem >> 10;
    int kin = rem & 1023;
    g_wk[i] = __float2half(w_conv[((size_t)n << 12) + (kin << 2) + t]);
}

// ------------------- chunked linear-recurrence scan -------------------
__global__ __launch_bounds__(256) void scan_pass1_k() {
    int c = blockIdx.y * 256 + threadIdx.x;
    int j = blockIdx.x;
    size_t base = (size_t)j * SCHUNK * DR + c;
    float A = 1.f, B = 0.f;
#pragma unroll 4
    for (int t = 0; t < SCHUNK; t++) {
        float at = g_a[base + (size_t)t * DR];
        float gx = g_gx[base + (size_t)t * DR];
        B = fmaf(at, B, gx);
        A *= at;
    }
    g_Ag[j * DR + c] = A;
    g_Bg[j * DR + c] = B;
}
__global__ __launch_bounds__(256) void scan_pass2_k() {
    int c = blockIdx.x * 256 + threadIdx.x;
    float h = 0.f;
    for (int j = 0; j < NCHUNK; j++) {
        g_carry[j * DR + c] = h;
        h = fmaf(g_Ag[j * DR + c], h, g_Bg[j * DR + c]);
    }
}
// pass3 fused with ya = a_branch * y, fp16 store
__global__ __launch_bounds__(256) void scan_pass3_k() {
    int c = blockIdx.y * 256 + threadIdx.x;
    int j = blockIdx.x;
    size_t base = (size_t)j * SCHUNK * DR + c;
    float h = g_carry[j * DR + c];
#pragma unroll 4
    for (int t = 0; t < SCHUNK; t++) {
        float at = g_a[base + (size_t)t * DR];
        float gx = g_gx[base + (size_t)t * DR];
        h = fmaf(at, h, gx);
        g_ya[base + (size_t)t * DR] = __float2half(h * __half2float(g_abr[base + (size_t)t * DR]));
    }
}

// ------------------- launch -------------------
#define STG_BYTES ((A_STG + B_STG) * 2)

extern "C" void kernel_launch(void* const* d_in, const int* in_sizes, int n_in,
                              void* d_out, int out_size) {
    const float* x      = (const float*)d_in[0];
    const float* w_n1   = (const float*)d_in[1];
    const float* w_n2   = (const float*)d_in[2];
    const float* w_lin1 = (const float*)d_in[3];
    const float* b_lin1 = (const float*)d_in[4];
    const float* w_conv = (const float*)d_in[5];
    const float* w_rg   = (const float*)d_in[6];
    const float* b_rg   = (const float*)d_in[7];
    const float* Lambda = (const float*)d_in[8];
    const float* w_out  = (const float*)d_in[9];
    const float* b_out  = (const float*)d_in[10];
    const float* w_m1   = (const float*)d_in[11];
    const float* b_m1   = (const float*)d_in[12];
    const float* w_m2   = (const float*)d_in[13];
    const float* b_m2   = (const float*)d_in[14];
    float* out = (float*)d_out;

    __half *p_hh, *p_abr, *p_bb, *p_convh, *p_ya, *p_mi;
    __half *p_wlin1i, *p_wrgi, *p_wout, *p_wm1i, *p_wm2, *p_wk;
    float *p_conv, *p_a, *p_gx, *p_x2;
    cudaGetSymbolAddress((void**)&p_hh, g_hh);
    cudaGetSymbolAddress((void**)&p_abr, g_abr);
    cudaGetSymbolAddress((void**)&p_bb, g_bb);
    cudaGetSymbolAddress((void**)&p_conv, g_conv);
    cudaGetSymbolAddress((void**)&p_convh, g_convh);
    cudaGetSymbolAddress((void**)&p_a, g_a);
    cudaGetSymbolAddress((void**)&p_gx, g_gx);
    cudaGetSymbolAddress((void**)&p_ya, g_ya);
    cudaGetSymbolAddress((void**)&p_x2, g_x2);
    cudaGetSymbolAddress((void**)&p_mi, g_mi);
    cudaGetSymbolAddress((void**)&p_wlin1i, g_wlin1i);
    cudaGetSymbolAddress((void**)&p_wrgi, g_wrgi);
    cudaGetSymbolAddress((void**)&p_wout, g_wout);
    cudaGetSymbolAddress((void**)&p_wm1i, g_wm1i);
    cudaGetSymbolAddress((void**)&p_wm2, g_wm2);
    cudaGetSymbolAddress((void**)&p_wk, g_wk);

    // Try 4 stages (216 KB); fall back to 3 (162 KB) if the attribute is rejected.
    int nstages = MAXSTAGES;
    if (cudaFuncSetAttribute(tc_gemm<0>, cudaFuncAttributeMaxDynamicSharedMemorySize,
                             MAXSTAGES * STG_BYTES) != cudaSuccess)
        nstages = 3;
    int smem_bytes = nstages * STG_BYTES;
    cudaFuncSetAttribute(tc_gemm<0>, cudaFuncAttributeMaxDynamicSharedMemorySize, smem_bytes);
    cudaFuncSetAttribute(tc_gemm<2>, cudaFuncAttributeMaxDynamicSharedMemorySize, smem_bytes);
    cudaFuncSetAttribute(tc_gemm<3>, cudaFuncAttributeMaxDynamicSharedMemorySize, smem_bytes);
    cudaFuncSetAttribute(tc_gemm<4>, cudaFuncAttributeMaxDynamicSharedMemorySize, smem_bytes);
    cudaFuncSetAttribute(tc_gemm<5>, cudaFuncAttributeMaxDynamicSharedMemorySize, smem_bytes);

    // Launch order keeps the conv GEMM at launch index 5 (ncu -s 5 -c 1 window).
    // [0] lin1 weight interleave
    cvt_w_pair_k<<<(2 * DR * DM + 255) / 256, 256>>>(w_lin1, p_wlin1i, DR, DM);
    // [1] conv weight repack
    repack_wconv_k<<<(DR * 4 * DR + 255) / 256, 256>>>(w_conv);
    // [2] h = rmsnorm(x, w_n1) -> fp16
    rmsnorm_k<<<S, 256>>>(x, w_n1, p_hh, DM);
    // [3] lin1 (interleaved): abr = gelu(a+b), bb = b_branch, both fp16
    tc_gemm<4><<<dim3(2 * DR / BN, S / BM), 256, smem_bytes>>>(
        p_hh, DM, p_wlin1i, b_lin1, nullptr, nullptr, DR, nullptr, p_bb, p_abr,
        nullptr, nullptr, DM, 0, nstages);
    // [4] rg weight interleave
    cvt_w_pair_k<<<(2 * DR * DR + 255) / 256, 256>>>(w_rg, p_wrgi, DR, DR);
    // [5] conv = causal conv as K=4096 GEMM (shifted A rows, zfill t<0)  <-- ncu window
    tc_gemm<0><<<dim3(DR / BN, S / BM), 256, smem_bytes>>>(
        p_bb, DR, p_wk, nullptr, nullptr, p_conv, DR, nullptr, p_convh, nullptr,
        nullptr, nullptr, 4 * DR, 1, nstages);
    // [6] gates GEMM (interleaved) with fused a/gated_x epilogue
    tc_gemm<2><<<dim3(2 * DR / BN, S / BM), 256, smem_bytes>>>(
        p_convh, DR, p_wrgi, b_rg, nullptr, p_a, DR, p_gx, nullptr, nullptr,
        p_conv, Lambda, DR, 0, nstages);
    // [7..9] linear recurrence scan (pass3 fused with ya = abr*y -> fp16)
    scan_pass1_k<<<dim3(NCHUNK, DR / 256), 256>>>();
    scan_pass2_k<<<DR / 256, 256>>>();
    scan_pass3_k<<<dim3(NCHUNK, DR / 256), 256>>>();
    // [10] out weight cvt
    cvt_w_k<<<(DM * DR / 4 + 255) / 256, 256>>>(w_out, p_wout, DM * DR);
    // [11] x2 = x + ya @ w_out^T + b_out   (fp32 residual path)
    tc_gemm<3><<<dim3(DM / BN, S / BM), 256, smem_bytes>>>(
        p_ya, DR, p_wout, b_out, x, p_x2, DM, nullptr, nullptr, nullptr,
        nullptr, nullptr, DR, 0, nstages);
    // [12] h2 = rmsnorm(x2, w_n2) -> fp16
    rmsnorm_k<<<S, 256>>>(p_x2, w_n2, p_hh, DM);
    // [13] m1 weight interleave
    cvt_w_pair_k<<<(2 * MI * DM + 255) / 256, 256>>>(w_m1, p_wm1i, MI, DM);
    // [14] m1 (interleaved) with fused GLU: mi = gelu(u)*v -> fp16
    tc_gemm<5><<<dim3(2 * MI / BN, S / BM), 256, smem_bytes>>>(
        p_hh, DM, p_wm1i, b_m1, nullptr, nullptr, MI, nullptr, p_mi, nullptr,
        nullptr, nullptr, DM, 0, nstages);
    // [15] m2 weight cvt
    cvt_w_k<<<(DM * MI / 4 + 255) / 256, 256>>>(w_m2, p_wm2, DM * MI);
    // [16] out = x2 + mi @ w_m2^T + b_m2   (fp32 residual path)
    tc_gemm<3><<<dim3(DM / BN, S / BM), 256, smem_bytes>>>(
        p_mi, MI, p_wm2, b_m2, p_x2, out, DM, nullptr, nullptr, nullptr,
        nullptr, nullptr, MI, 0, nstages);
}

// round 16
// speedup vs baseline: 1.0516x; 1.0516x over previous
#include <cuda_runtime.h>
#include <cuda_fp16.h>
#include <math.h>
#include <stdint.h>

#define S 8192
#define DM 768
#define DR 1024
#define MI 3072

// ------------------- scratch (device globals; no allocs allowed) -------------------
__device__ __half g_hh[S * DM];          // rmsnorm output (h, then h2), fp16
__device__ __half g_abr[S * DR];         // gelu(a_branch), fp16
__device__ __half g_bb[S * DR];          // b_branch, fp16
__device__ float  g_conv[S * DR];        // conv output fp32 (for gx math)
__device__ __half g_convh[S * DR];       // conv output fp16 (gates GEMM operand)
__device__ float  g_a[S * DR];           // recurrence decay
__device__ float  g_gx[S * DR];          // gated_x
__device__ __half g_ya[S * DR];          // a_branch * y, fp16 (out-GEMM operand)
__device__ float  g_x2[S * DM];          // x + tempmix
__device__ __half g_mi[S * MI];          // GLU output, fp16 (m2-GEMM operand)
// fp16 weights (converted once per launch; *_i = row-interleaved pairs)
__device__ __half g_wlin1i[2 * DR * DM];
__device__ __half g_wk[DR * 4 * DR];     // conv repacked [N=1024][K=4096]
__device__ __half g_wrgi[2 * DR * DR];
__device__ __half g_wout[DM * DR];
__device__ __half g_wm1i[2 * MI * DM];
__device__ __half g_wm2[DM * MI];
#define NCHUNK 64
#define SCHUNK 128
__device__ float g_Ag[NCHUNK * DR];
__device__ float g_Bg[NCHUNK * DR];
__device__ float g_carry[NCHUNK * DR];

// ------------------- math helpers -------------------
__device__ __forceinline__ float gelu_f(float x) {
    float x3 = x * x * x;
    return 0.5f * x * (1.0f + tanhf(0.7978845608028654f * (x + 0.044715f * x3)));
}
__device__ __forceinline__ float sigmoid_f(float x) { return 1.0f / (1.0f + expf(-x)); }

// ------------------- cp.async / ldmatrix helpers -------------------
__device__ __forceinline__ uint32_t smem_u32(const void* p) {
    uint32_t a;
    asm("{ .reg .u64 t; cvta.to.shared.u64 t, %1; cvt.u32.u64 %0, t; }" : "=r"(a) : "l"(p));
    return a;
}
#define CP16(dst, src) \
    asm volatile("cp.async.cg.shared.global [%0], [%1], 16;" :: "r"(dst), "l"(src))
#define CP16_ZFILL(dst, src) \
    asm volatile("cp.async.cg.shared.global [%0], [%1], 16, 0;" :: "r"(dst), "l"(src))
#define CP_COMMIT() asm volatile("cp.async.commit_group;" ::: "memory")
#define CP_WAIT(n) asm volatile("cp.async.wait_group %0;" :: "n"(n) : "memory")
#define LDSM_X4(r0, r1, r2, r3, addr)                                           \
    asm volatile("ldmatrix.sync.aligned.m8n8.x4.shared.b16 {%0,%1,%2,%3}, [%4];" \
                 : "=r"(r0), "=r"(r1), "=r"(r2), "=r"(r3) : "r"(addr))

// ------------------- fp16 mma.sync m16n8k16 (fp32 accum) -------------------
__device__ __forceinline__ void mma_f16(float* c, const uint32_t* a, const uint32_t* b) {
    asm volatile(
        "mma.sync.aligned.m16n8k16.row.col.f32.f16.f16.f32 "
        "{%0,%1,%2,%3}, {%4,%5,%6,%7}, {%8,%9}, {%0,%1,%2,%3};"
        : "+f"(c[0]), "+f"(c[1]), "+f"(c[2]), "+f"(c[3])
        : "r"(a[0]), "r"(a[1]), "r"(a[2]), "r"(a[3]), "r"(b[0]), "r"(b[1]));
}

// ------------------- fp16 GEMM: C[M,N] = A[M,K] @ W[N,K]^T (+fused epilogues) ------
// Tile 256x128x64, 512 threads (4x4 warps), warp tile 64x32, up-to-4-stage cp.async.
// Same per-warp body as the R12 winner (6 LDSM / 16 MMA per k16, 128 regs), but
// 16 warps in ONE CTA with 0.75x cp.async bytes/FLOP and a deeper pipeline.
// EPI 0: conv      -> C fp32 + Cb fp16
// EPI 2: gates     -> pairwise (ig,rg): a=exp(-8 sp(lam) rg), gx=sqrt(1-a^2) ig conv
// EPI 3: +bias+res -> C fp32 (out / m2)
// EPI 4: lin1      -> pairwise: Cb2=gelu(a+bias) fp16, Cb=b+bias fp16
// EPI 5: m1+GLU    -> pairwise: Cb=gelu(u)*v fp16
#define MAXSTAGES 4
#define NT 512
#define BM 256
#define BN 128
#define BK 64
#define SK 72                          // padded row stride in halves (64+8 -> 144B)
#define A_STG (BM * SK)                // halves per A stage
#define B_STG (BN * SK)                // halves per B stage

template <int EPI>
__global__ void __launch_bounds__(NT)
tc_gemm(const __half* __restrict__ A, int lda, const __half* __restrict__ W,
        const float* __restrict__ bias, const float* __restrict__ res,
        float* __restrict__ C, int ldc, float* __restrict__ C2,
        __half* __restrict__ Cb, __half* __restrict__ Cb2,
        const float* __restrict__ aux, const float* __restrict__ lam,
        int K, int shifted, int nstages) {
    extern __shared__ __half sm[];
    __half* sA = sm;                           // nstages * A_STG
    __half* sB = sm + nstages * A_STG;         // nstages * B_STG
    const int tid = threadIdx.x, lane = tid & 31, wid = tid >> 5;
    const int wm = wid & 3, wn = wid >> 2, laneg = lane >> 2, lanet = lane & 3;
    const int bm = blockIdx.y * BM, bn = blockIdx.x * BN;
    const int ktiles = K >> 6;
    const uint32_t sAaddr = smem_u32(sA), sBaddr = smem_u32(sB);

    // ldmatrix lane-address bases (bytes), before stage/k/frag offsets
    const uint32_t aBase = sAaddr +
        (uint32_t)((wm * 64 + (lane & 15)) * SK + ((lane >> 4) << 3)) * 2u;
    const uint32_t bBase = sBaddr +
        (uint32_t)((wn * 32 + (lane & 7) + (((lane >> 4) & 1) << 3)) * SK +
                   (((lane >> 3) & 1) << 3)) * 2u;

    float acc[4][4][4];
#pragma unroll
    for (int i = 0; i < 4; i++)
#pragma unroll
        for (int j = 0; j < 4; j++)
#pragma unroll
            for (int t = 0; t < 4; t++) acc[i][j][t] = 0.f;

    auto load_stage = [&](int kt, int st) {
#pragma unroll
        for (int i = 0; i < 4; i++) {                 // A: 2048 16B chunks (256 rows x 64 halves)
            int c = tid + NT * i;
            int row = c >> 3, kc = c & 7;
            int grow, gcol;
            if (shifted) { int seg = kt >> 4; grow = bm + row + seg - 3; gcol = ((kt & 15) << 6) + (kc << 3); }
            else { grow = bm + row; gcol = (kt << 6) + (kc << 3); }
            uint32_t dst = sAaddr + (uint32_t)(st * A_STG + row * SK + (kc << 3)) * 2u;
            const __half* src = A + (size_t)grow * lda + gcol;
            if (shifted && grow < 0) CP16_ZFILL(dst, A);
            else CP16(dst, src);
        }
#pragma unroll
        for (int i = 0; i < 2; i++) {                 // B: 1024 16B chunks (128 rows)
            int c = tid + NT * i;
            int row = c >> 3, kc = c & 7;
            uint32_t dst = sBaddr + (uint32_t)(st * B_STG + row * SK + (kc << 3)) * 2u;
            const __half* src = W + (size_t)(bn + row) * K + (kt << 6) + (kc << 3);
            CP16(dst, src);
        }
    };

    auto compute_stage = [&](int st) {
        const uint32_t aoff = (uint32_t)(st * A_STG) * 2u;
        const uint32_t boff = (uint32_t)(st * B_STG) * 2u;
#pragma unroll
        for (int k16 = 0; k16 < 4; k16++) {
            const uint32_t kb = (uint32_t)(k16 * 16) * 2u;
            uint32_t af[4][4], bf[4][2];
#pragma unroll
            for (int mf = 0; mf < 4; mf++) {
                uint32_t addr = aBase + aoff + (uint32_t)(mf * 16 * SK) * 2u + kb;
                LDSM_X4(af[mf][0], af[mf][1], af[mf][2], af[mf][3], addr);
            }
#pragma unroll
            for (int np = 0; np < 2; np++) {
                uint32_t addr = bBase + boff + (uint32_t)(np * 16 * SK) * 2u + kb;
                LDSM_X4(bf[2 * np][0], bf[2 * np][1], bf[2 * np + 1][0], bf[2 * np + 1][1], addr);
            }
#pragma unroll
            for (int mf = 0; mf < 4; mf++)
#pragma unroll
                for (int nf = 0; nf < 4; nf++) mma_f16(acc[mf][nf], af[mf], bf[nf]);
        }
    };

    for (int s = 0; s < nstages - 1; s++) { load_stage(s, s); CP_COMMIT(); }
    int st = 0;
    for (int kt = 0; kt < ktiles; kt++) {
        if (nstages == 4) CP_WAIT(2); else CP_WAIT(1);
        __syncthreads();
        int nk = kt + nstages - 1;
        if (nk < ktiles) load_stage(nk, (st + nstages - 1) % nstages);
        CP_COMMIT();
        compute_stage(st);
        if (++st == nstages) st = 0;
    }
    CP_WAIT(0);

    // ---------------- epilogues ----------------
    if (EPI == 0 || EPI == 3) {
#pragma unroll
        for (int mf = 0; mf < 4; mf++)
#pragma unroll
            for (int half = 0; half < 2; half++) {
                int row = bm + wm * 64 + mf * 16 + laneg + half * 8;
                size_t crow = (size_t)row * ldc;
#pragma unroll
                for (int nf = 0; nf < 4; nf++) {
                    int col = bn + wn * 32 + nf * 8 + lanet * 2;
                    float v0 = acc[mf][nf][half * 2];
                    float v1 = acc[mf][nf][half * 2 + 1];
                    if (EPI == 3) {
                        v0 += bias[col] + res[crow + col];
                        v1 += bias[col + 1] + res[crow + col + 1];
                    }
                    *(float2*)&C[crow + col] = make_float2(v0, v1);
                    if (EPI == 0) {
                        __half2 hv; hv.x = __float2half(v0); hv.y = __float2half(v1);
                        *(__half2*)&Cb[crow + col] = hv;
                    }
                }
            }
    } else {  // pairwise EPIs: thread holds (2c, 2c+1)
#pragma unroll
        for (int nf = 0; nf < 4; nf++) {
            int c = (bn + wn * 32 + nf * 8 + lanet * 2) >> 1;
            float sp, b0, b1;
            if (EPI == 2) { sp = log1pf(expf(lam[c])); b0 = bias[c]; b1 = bias[DR + c]; }
            if (EPI == 4) { b0 = bias[c]; b1 = bias[DR + c]; }
            if (EPI == 5) { b0 = bias[c]; b1 = bias[MI + c]; }
#pragma unroll
            for (int mf = 0; mf < 4; mf++)
#pragma unroll
                for (int half = 0; half < 2; half++) {
                    int row = bm + wm * 64 + mf * 16 + laneg + half * 8;
                    float v0 = acc[mf][nf][half * 2] + b0;
                    float v1 = acc[mf][nf][half * 2 + 1] + b1;
                    if (EPI == 2) {
                        float ig = sigmoid_f(v0), rg = sigmoid_f(v1);
                        float a = expf(-8.0f * sp * rg);
                        float gx = sqrtf(fmaxf(1.0f - a * a, 0.f)) * ig * aux[(size_t)row * DR + c];
                        C[(size_t)row * DR + c] = a;
                        C2[(size_t)row * DR + c] = gx;
                    } else if (EPI == 4) {
                        Cb2[(size_t)row * DR + c] = __float2half(gelu_f(v0));
                        Cb[(size_t)row * DR + c] = __float2half(v1);
                    } else {  // EPI 5
                        Cb[(size_t)row * MI + c] = __float2half(gelu_f(v0) * v1);
                    }
                }
        }
    }
}

// ------------------- RMSNorm (fp16 output: feeds GEMMs) -------------------
__global__ __launch_bounds__(256) void rmsnorm_k(const float* __restrict__ x,
                                                 const float* __restrict__ w,
                                                 __half* __restrict__ o, int D) {
    int row = blockIdx.x;
    const float* xr = x + (size_t)row * D;
    float s = 0.f;
    for (int i = threadIdx.x; i < D; i += 256) { float v = xr[i]; s += v * v; }
    __shared__ float sm[8];
    __shared__ float s_inv;
    for (int off = 16; off; off >>= 1) s += __shfl_down_sync(0xffffffffu, s, off);
    if ((threadIdx.x & 31) == 0) sm[threadIdx.x >> 5] = s;
    __syncthreads();
    if (threadIdx.x == 0) {
        float t = 0.f;
#pragma unroll
        for (int i = 0; i < 8; i++) t += sm[i];
        s_inv = rsqrtf(t / (float)D + 1e-5f);
    }
    __syncthreads();
    float inv = s_inv;
    __half* orow = o + (size_t)row * D;
    for (int i = threadIdx.x; i < D; i += 256) orow[i] = __float2half(xr[i] * inv * w[i]);
}

// ------------------- weight conversion kernels -------------------
__global__ __launch_bounds__(256) void cvt_w_k(const float* __restrict__ src,
                                               __half* __restrict__ dst, int n) {
    int i = (blockIdx.x * 256 + threadIdx.x) * 4;
    if (i >= n) return;
    float4 v = *(const float4*)(src + i);
    __half2 h0; h0.x = __float2half(v.x); h0.y = __float2half(v.y);
    __half2 h1; h1.x = __float2half(v.z); h1.y = __float2half(v.w);
    *(__half2*)(dst + i) = h0;
    *(__half2*)(dst + i + 2) = h1;
}
// interleave rows: dst[2c+p][k] = src[p*Nh + c][k]
__global__ __launch_bounds__(256) void cvt_w_pair_k(const float* __restrict__ src,
                                                    __half* __restrict__ dst, int Nh, int K) {
    int i = blockIdx.x * 256 + threadIdx.x;
    if (i >= 2 * Nh * K) return;
    int n = i / K, k = i - n * K;
    int c = n >> 1, p = n & 1;
    dst[i] = __float2half(src[(size_t)(p * Nh + c) * K + k]);
}
__global__ __launch_bounds__(256) void repack_wconv_k(const float* __restrict__ w_conv) {
    int i = blockIdx.x * 256 + threadIdx.x;
    if (i >= DR * 4 * DR) return;
    int n = i >> 12;
    int rem = i & 4095;
    int t = rem >> 10;
    int kin = rem & 1023;
    g_wk[i] = __float2half(w_conv[((size_t)n << 12) + (kin << 2) + t]);
}

// ------------------- chunked linear-recurrence scan -------------------
__global__ __launch_bounds__(256) void scan_pass1_k() {
    int c = blockIdx.y * 256 + threadIdx.x;
    int j = blockIdx.x;
    size_t base = (size_t)j * SCHUNK * DR + c;
    float A = 1.f, B = 0.f;
#pragma unroll 4
    for (int t = 0; t < SCHUNK; t++) {
        float at = g_a[base + (size_t)t * DR];
        float gx = g_gx[base + (size_t)t * DR];
        B = fmaf(at, B, gx);
        A *= at;
    }
    g_Ag[j * DR + c] = A;
    g_Bg[j * DR + c] = B;
}
__global__ __launch_bounds__(256) void scan_pass2_k() {
    int c = blockIdx.x * 256 + threadIdx.x;
    float h = 0.f;
    for (int j = 0; j < NCHUNK; j++) {
        g_carry[j * DR + c] = h;
        h = fmaf(g_Ag[j * DR + c], h, g_Bg[j * DR + c]);
    }
}
// pass3 fused with ya = a_branch * y, fp16 store
__global__ __launch_bounds__(256) void scan_pass3_k() {
    int c = blockIdx.y * 256 + threadIdx.x;
    int j = blockIdx.x;
    size_t base = (size_t)j * SCHUNK * DR + c;
    float h = g_carry[j * DR + c];
#pragma unroll 4
    for (int t = 0; t < SCHUNK; t++) {
        float at = g_a[base + (size_t)t * DR];
        float gx = g_gx[base + (size_t)t * DR];
        h = fmaf(at, h, gx);
        g_ya[base + (size_t)t * DR] = __float2half(h * __half2float(g_abr[base + (size_t)t * DR]));
    }
}

// ------------------- launch -------------------
#define STG_BYTES ((A_STG + B_STG) * 2)

extern "C" void kernel_launch(void* const* d_in, const int* in_sizes, int n_in,
                              void* d_out, int out_size) {
    const float* x      = (const float*)d_in[0];
    const float* w_n1   = (const float*)d_in[1];
    const float* w_n2   = (const float*)d_in[2];
    const float* w_lin1 = (const float*)d_in[3];
    const float* b_lin1 = (const float*)d_in[4];
    const float* w_conv = (const float*)d_in[5];
    const float* w_rg   = (const float*)d_in[6];
    const float* b_rg   = (const float*)d_in[7];
    const float* Lambda = (const float*)d_in[8];
    const float* w_out  = (const float*)d_in[9];
    const float* b_out  = (const float*)d_in[10];
    const float* w_m1   = (const float*)d_in[11];
    const float* b_m1   = (const float*)d_in[12];
    const float* w_m2   = (const float*)d_in[13];
    const float* b_m2   = (const float*)d_in[14];
    float* out = (float*)d_out;

    __half *p_hh, *p_abr, *p_bb, *p_convh, *p_ya, *p_mi;
    __half *p_wlin1i, *p_wrgi, *p_wout, *p_wm1i, *p_wm2, *p_wk;
    float *p_conv, *p_a, *p_gx, *p_x2;
    cudaGetSymbolAddress((void**)&p_hh, g_hh);
    cudaGetSymbolAddress((void**)&p_abr, g_abr);
    cudaGetSymbolAddress((void**)&p_bb, g_bb);
    cudaGetSymbolAddress((void**)&p_conv, g_conv);
    cudaGetSymbolAddress((void**)&p_convh, g_convh);
    cudaGetSymbolAddress((void**)&p_a, g_a);
    cudaGetSymbolAddress((void**)&p_gx, g_gx);
    cudaGetSymbolAddress((void**)&p_ya, g_ya);
    cudaGetSymbolAddress((void**)&p_x2, g_x2);
    cudaGetSymbolAddress((void**)&p_mi, g_mi);
    cudaGetSymbolAddress((void**)&p_wlin1i, g_wlin1i);
    cudaGetSymbolAddress((void**)&p_wrgi, g_wrgi);
    cudaGetSymbolAddress((void**)&p_wout, g_wout);
    cudaGetSymbolAddress((void**)&p_wm1i, g_wm1i);
    cudaGetSymbolAddress((void**)&p_wm2, g_wm2);
    cudaGetSymbolAddress((void**)&p_wk, g_wk);

    // Try 4 stages (221 KB); fall back to 3 (166 KB) if the attribute is rejected.
    int nstages = MAXSTAGES;
    if (cudaFuncSetAttribute(tc_gemm<0>, cudaFuncAttributeMaxDynamicSharedMemorySize,
                             MAXSTAGES * STG_BYTES) != cudaSuccess)
        nstages = 3;
    int smem_bytes = nstages * STG_BYTES;
    cudaFuncSetAttribute(tc_gemm<0>, cudaFuncAttributeMaxDynamicSharedMemorySize, smem_bytes);
    cudaFuncSetAttribute(tc_gemm<2>, cudaFuncAttributeMaxDynamicSharedMemorySize, smem_bytes);
    cudaFuncSetAttribute(tc_gemm<3>, cudaFuncAttributeMaxDynamicSharedMemorySize, smem_bytes);
    cudaFuncSetAttribute(tc_gemm<4>, cudaFuncAttributeMaxDynamicSharedMemorySize, smem_bytes);
    cudaFuncSetAttribute(tc_gemm<5>, cudaFuncAttributeMaxDynamicSharedMemorySize, smem_bytes);

    // Launch order keeps the conv GEMM at launch index 5 (ncu -s 5 -c 1 window).
    // [0] lin1 weight interleave
    cvt_w_pair_k<<<(2 * DR * DM + 255) / 256, 256>>>(w_lin1, p_wlin1i, DR, DM);
    // [1] conv weight repack
    repack_wconv_k<<<(DR * 4 * DR + 255) / 256, 256>>>(w_conv);
    // [2] h = rmsnorm(x, w_n1) -> fp16
    rmsnorm_k<<<S, 256>>>(x, w_n1, p_hh, DM);
    // [3] lin1 (interleaved): abr = gelu(a+b), bb = b_branch, both fp16
    tc_gemm<4><<<dim3(2 * DR / BN, S / BM), NT, smem_bytes>>>(
        p_hh, DM, p_wlin1i, b_lin1, nullptr, nullptr, DR, nullptr, p_bb, p_abr,
        nullptr, nullptr, DM, 0, nstages);
    // [4] rg weight interleave
    cvt_w_pair_k<<<(2 * DR * DR + 255) / 256, 256>>>(w_rg, p_wrgi, DR, DR);
    // [5] conv = causal conv as K=4096 GEMM (shifted A rows, zfill t<0)  <-- ncu window
    tc_gemm<0><<<dim3(DR / BN, S / BM), NT, smem_bytes>>>(
        p_bb, DR, p_wk, nullptr, nullptr, p_conv, DR, nullptr, p_convh, nullptr,
        nullptr, nullptr, 4 * DR, 1, nstages);
    // [6] gates GEMM (interleaved) with fused a/gated_x epilogue
    tc_gemm<2><<<dim3(2 * DR / BN, S / BM), NT, smem_bytes>>>(
        p_convh, DR, p_wrgi, b_rg, nullptr, p_a, DR, p_gx, nullptr, nullptr,
        p_conv, Lambda, DR, 0, nstages);
    // [7..9] linear recurrence scan (pass3 fused with ya = abr*y -> fp16)
    scan_pass1_k<<<dim3(NCHUNK, DR / 256), 256>>>();
    scan_pass2_k<<<DR / 256, 256>>>();
    scan_pass3_k<<<dim3(NCHUNK, DR / 256), 256>>>();
    // [10] out weight cvt
    cvt_w_k<<<(DM * DR / 4 + 255) / 256, 256>>>(w_out, p_wout, DM * DR);
    // [11] x2 = x + ya @ w_out^T + b_out   (fp32 residual path)
    tc_gemm<3><<<dim3(DM / BN, S / BM), NT, smem_bytes>>>(
        p_ya, DR, p_wout, b_out, x, p_x2, DM, nullptr, nullptr, nullptr,
        nullptr, nullptr, DR, 0, nstages);
    // [12] h2 = rmsnorm(x2, w_n2) -> fp16
    rmsnorm_k<<<S, 256>>>(p_x2, w_n2, p_hh, DM);
    // [13] m1 weight interleave
    cvt_w_pair_k<<<(2 * MI * DM + 255) / 256, 256>>>(w_m1, p_wm1i, MI, DM);
    // [14] m1 (interleaved) with fused GLU: mi = gelu(u)*v -> fp16
    tc_gemm<5><<<dim3(2 * MI / BN, S / BM), NT, smem_bytes>>>(
        p_hh, DM, p_wm1i, b_m1, nullptr, nullptr, MI, nullptr, p_mi, nullptr,
        nullptr, nullptr, DM, 0, nstages);
    // [15] m2 weight cvt
    cvt_w_k<<<(DM * MI / 4 + 255) / 256, 256>>>(w_m2, p_wm2, DM * MI);
    // [16] out = x2 + mi @ w_m2^T + b_m2   (fp32 residual path)
    tc_gemm<3><<<dim3(DM / BN, S / BM), NT, smem_bytes>>>(
        p_mi, MI, p_wm2, b_m2, p_x2, out, DM, nullptr, nullptr, nullptr,
        nullptr, nullptr, MI, 0, nstages);
}